// round 14
// baseline (speedup 1.0000x reference)
#include <cuda_runtime.h>
#include <cuda_fp16.h>
#include <cstdint>

// ----------------------------------------------------------------------------
// Problem constants
// ----------------------------------------------------------------------------
#define Bc   4
#define Sc   2048
#define Dc   768
#define Hc   12
#define HDc  64
#define Mrows (Bc * Sc)   // 8192

// Scratch (device globals)
__device__ __half g_q [(size_t)Mrows * Dc];
__device__ __half g_k [(size_t)Mrows * Dc];
__device__ __half g_v [(size_t)Mrows * Dc];
__device__ __half g_hs[(size_t)Mrows * Dc];
__device__ __half g_lq[(size_t)Mrows * Dc];
__device__ __half g_lk[(size_t)Mrows * Dc];
__device__ __half g_wq[(size_t)Dc * Dc];
__device__ __half g_wk[(size_t)Dc * Dc];
__device__ __half g_wv[(size_t)Dc * Dc];
__device__ float  g_mkl[(size_t)Bc * Sc];   // mask * log2(e) - 8

// ----------------------------------------------------------------------------
// Helpers
// ----------------------------------------------------------------------------
__device__ __forceinline__ uint32_t smem_u32(const void* p) {
    uint32_t a;
    asm("{ .reg .u64 t; cvta.to.shared.u64 t, %1; cvt.u32.u64 %0, t; }" : "=r"(a) : "l"(p));
    return a;
}
__device__ __forceinline__ void cpa16(uint32_t dst, const void* src) {
    asm volatile("cp.async.cg.shared.global [%0], [%1], 16;" :: "r"(dst), "l"(src));
}
#define CPA_COMMIT() asm volatile("cp.async.commit_group;" ::: "memory")
#define CPA_WAIT(N)  asm volatile("cp.async.wait_group %0;" :: "n"(N) : "memory")

__device__ __forceinline__ float ex2(float x) {
    float r;
    asm("ex2.approx.f32 %0, %1;" : "=f"(r) : "f"(x));
    return r;
}

__device__ __forceinline__ void ldsm4(uint32_t& r0, uint32_t& r1, uint32_t& r2, uint32_t& r3,
                                      uint32_t addr) {
    asm volatile("ldmatrix.sync.aligned.m8n8.x4.shared.b16 {%0,%1,%2,%3}, [%4];"
                 : "=r"(r0), "=r"(r1), "=r"(r2), "=r"(r3) : "r"(addr));
}
__device__ __forceinline__ void ldsm4t(uint32_t& r0, uint32_t& r1, uint32_t& r2, uint32_t& r3,
                                       uint32_t addr) {
    asm volatile("ldmatrix.sync.aligned.m8n8.x4.trans.shared.b16 {%0,%1,%2,%3}, [%4];"
                 : "=r"(r0), "=r"(r1), "=r"(r2), "=r"(r3) : "r"(addr));
}
__device__ __forceinline__ void ldsm2t(uint32_t& r0, uint32_t& r1, uint32_t addr) {
    asm volatile("ldmatrix.sync.aligned.m8n8.x2.trans.shared.b16 {%0,%1}, [%2];"
                 : "=r"(r0), "=r"(r1) : "r"(addr));
}

// d += a @ b  (m16n8k16, fp16 inputs, f32 accum)
__device__ __forceinline__ void mma16(float* d, const uint32_t* a, const uint32_t* b) {
    asm volatile(
        "mma.sync.aligned.m16n8k16.row.col.f32.f16.f16.f32 "
        "{%0,%1,%2,%3}, {%4,%5,%6,%7}, {%8,%9}, {%0,%1,%2,%3};\n"
        : "+f"(d[0]), "+f"(d[1]), "+f"(d[2]), "+f"(d[3])
        : "r"(a[0]), "r"(a[1]), "r"(a[2]), "r"(a[3]), "r"(b[0]), "r"(b[1]));
}

__device__ __forceinline__ uint32_t h2pack(float a, float b) {
    __half2 h = __floats2half2_rn(a, b);
    return *reinterpret_cast<uint32_t*>(&h);
}

__device__ __forceinline__ void cvt_arr(const float* __restrict__ s, __half* __restrict__ d,
                                        int n8, int idx, int stride) {
    for (int i = idx; i < n8; i += stride) {
        float4 v0 = ((const float4*)s)[2 * i];
        float4 v1 = ((const float4*)s)[2 * i + 1];
        uint4 o;
        o.x = h2pack(v0.x, v0.y);
        o.y = h2pack(v0.z, v0.w);
        o.z = h2pack(v1.x, v1.y);
        o.w = h2pack(v1.z, v1.w);
        ((uint4*)d)[i] = o;
    }
}

// ----------------------------------------------------------------------------
// Prep stage A: hs + weights (consumed by linear kernel) — must run first
// ----------------------------------------------------------------------------
__global__ void prep_a(const float* __restrict__ hs, const float* __restrict__ wq,
                       const float* __restrict__ wk, const float* __restrict__ wv)
{
    const int which = blockIdx.y;
    int idx = blockIdx.x * blockDim.x + threadIdx.x;
    int stride = gridDim.x * blockDim.x;
    if (which == 0)      cvt_arr(hs, g_hs, (Mrows * Dc) / 8, idx, stride);
    else if (which == 1) cvt_arr(wq, g_wq, (Dc * Dc) / 8, idx, stride);
    else if (which == 2) cvt_arr(wk, g_wk, (Dc * Dc) / 8, idx, stride);
    else                 cvt_arr(wv, g_wv, (Dc * Dc) / 8, idx, stride);
}

// ----------------------------------------------------------------------------
// Linear: Y = X @ W^T + b  (fp16 m16n8k16 + ldmatrix, 128x128x32)
// 3-stage cp.async pipeline. grid.z==3 slice does prep-B (lq/lk/mask convert),
// co-scheduled with the tensor-bound GEMM CTAs (DRAM-idle overlap).
// ----------------------------------------------------------------------------
#define LSTR 40
#define LIN_STAGE_H (128 * LSTR)
#define LIN_SMEM (6 * LIN_STAGE_H * 2)           // 61440 B

__global__ __launch_bounds__(256, 2) void linear_tc(
    const float* __restrict__ bq,
    const float* __restrict__ bk,
    const float* __restrict__ bv,
    const float* __restrict__ lq_f32,
    const float* __restrict__ lk_f32,
    const float* __restrict__ mask)
{
    const int z = blockIdx.z;
    const int tid = threadIdx.x;

    if (z == 3) {
        // ---- prep B: convert lq, lk (fp16) and mask (f32*log2e - 8)
        const int cta = blockIdx.y * gridDim.x + blockIdx.x;   // 0..383
        const int nctas = gridDim.x * gridDim.y;               // 384
        int idx = cta * 256 + tid;
        int stride = nctas * 256;
        cvt_arr(lq_f32, g_lq, (Mrows * Dc) / 8, idx, stride);
        cvt_arr(lk_f32, g_lk, (Mrows * Dc) / 8, idx, stride);
        const float L2E = 1.4426950408889634f;
        const int n4 = (Bc * Sc) / 4;
        for (int i = idx; i < n4; i += stride) {
            float4 v = ((const float4*)mask)[i];
            v.x = v.x * L2E - 8.0f; v.y = v.y * L2E - 8.0f;
            v.z = v.z * L2E - 8.0f; v.w = v.w * L2E - 8.0f;
            ((float4*)g_mkl)[i] = v;
        }
        return;
    }

    extern __shared__ __align__(16) __half smh[];
    const uint32_t smb = smem_u32(smh);

    const __half* X    = g_hs;
    const __half* W    = (z == 0) ? g_wq : (z == 1) ? g_wk : g_wv;
    const float* bias  = (z == 0) ? bq   : (z == 1) ? bk   : bv;
    __half* Y          = (z == 0) ? g_q  : (z == 1) ? g_k  : g_v;

    const int wid = tid >> 5, lane = tid & 31;
    const int g = lane >> 2, tig = lane & 3;
    const int warpm = wid >> 1, warpn = wid & 1;
    const int bm = blockIdx.y * 128, bn = blockIdx.x * 128;

    auto issue = [&](int it) {
        const int st = it % 3;
        const int k0 = it * 32;
        const uint32_t ab = smb + (uint32_t)(st * 2 * LIN_STAGE_H) * 2;
        const uint32_t bb = ab + (uint32_t)LIN_STAGE_H * 2;
#pragma unroll
        for (int i = 0; i < 2; i++) {
            int id = tid + i * 256;
            int row = id >> 2, ch = id & 3;
            uint32_t off = (uint32_t)(row * LSTR + ch * 8) * 2;
            cpa16(ab + off, X + (size_t)(bm + row) * Dc + k0 + ch * 8);
            cpa16(bb + off, W + (size_t)(bn + row) * Dc + k0 + ch * 8);
        }
        CPA_COMMIT();
    };

    float acc[2][8][4];
#pragma unroll
    for (int mt = 0; mt < 2; mt++)
#pragma unroll
        for (int nt = 0; nt < 8; nt++)
#pragma unroll
            for (int c = 0; c < 4; c++) acc[mt][nt][c] = 0.0f;

    const uint32_t a_loff = ((uint32_t)(warpm * 32 + (lane & 15)) * LSTR + ((lane >> 4) << 3)) * 2;
    const uint32_t b_loff = ((uint32_t)(warpn * 64 + (lane & 15)) * LSTR + ((lane >> 4) << 3)) * 2;

    issue(0);
    issue(1);
    for (int it = 0; it < 24; it++) {
        if (it == 23) { CPA_WAIT(0); } else { CPA_WAIT(1); }
        __syncthreads();
        if (it < 22) issue(it + 2);

        const int st = it % 3;
        const uint32_t ab = smb + (uint32_t)(st * 2 * LIN_STAGE_H) * 2 + a_loff;
        const uint32_t bb = smb + (uint32_t)(st * 2 * LIN_STAGE_H + LIN_STAGE_H) * 2 + b_loff;

#pragma unroll
        for (int kc = 0; kc < 2; kc++) {
            uint32_t afr[2][4];
#pragma unroll
            for (int mt = 0; mt < 2; mt++)
                ldsm4(afr[mt][0], afr[mt][1], afr[mt][2], afr[mt][3],
                      ab + ((uint32_t)(mt * 16 * LSTR + kc * 16) << 1));
#pragma unroll
            for (int ntp = 0; ntp < 4; ntp++) {
                uint32_t m0, m1, m2, m3;
                ldsm4(m0, m1, m2, m3, bb + ((uint32_t)(ntp * 16 * LSTR + kc * 16) << 1));
                uint32_t b0[2] = {m0, m2}, b1[2] = {m1, m3};
#pragma unroll
                for (int mt = 0; mt < 2; mt++) {
                    mma16(acc[mt][2 * ntp],     afr[mt], b0);
                    mma16(acc[mt][2 * ntp + 1], afr[mt], b1);
                }
            }
        }
    }

#pragma unroll
    for (int mt = 0; mt < 2; mt++) {
        const int row0 = bm + warpm * 32 + mt * 16 + g;
#pragma unroll
        for (int nt = 0; nt < 8; nt++) {
            const int col = bn + warpn * 64 + nt * 8 + 2 * tig;
            const float bx = bias[col], by = bias[col + 1];
            *(uint32_t*)&Y[(size_t)row0 * Dc + col] =
                h2pack(acc[mt][nt][0] + bx, acc[mt][nt][1] + by);
            *(uint32_t*)&Y[(size_t)(row0 + 8) * Dc + col] =
                h2pack(acc[mt][nt][2] + bx, acc[mt][nt][3] + by);
        }
    }
}

// ----------------------------------------------------------------------------
// Flash attention (fp16 m16n8k16): fixed-shift softmax, ones-column l.
// 32 q-rows per warp. CTA = (b, h, 256-q tile), 8 warps, KT=32, occ 1.
// (R12-verified kernel, unchanged.)
// ----------------------------------------------------------------------------
#define KT 32
#define NT 64                           // Sc / KT
#define KSTR 136
#define VSTR 72
#define KSBUF (KT * KSTR)               // 4352 halfs
#define VSBUF (KT * VSTR)               // 2304 halfs
#define KS_H 0                          // 4 bufs
#define VS_H (4 * KSBUF)                // 17408
#define MS_B ((VS_H + 4 * VSBUF) * 2)   // 53248 bytes
#define QS_B (MS_B + 4 * KT * 4)        // 53760 bytes (Q staging region)
#define ATT_SMEM (QS_B + 256 * KSTR * 2)  // 123392 B

__global__ __launch_bounds__(256, 1) void attn_tc(
    float* __restrict__ out)
{
    extern __shared__ __align__(16) __half smh[];
    const uint32_t smb = smem_u32(smh);
    float* msf = (float*)((char*)smh + MS_B);

    const int tid = threadIdx.x;
    const int wid = tid >> 5, lane = tid & 31;
    const int g = lane >> 2, tig = lane & 3;

    const int b = blockIdx.z, h = blockIdx.y, q0 = blockIdx.x * 256;
    const int hoff = h * HDc;

    auto issue_tile = [&](int t) {
        const int s = t & 3;
        const size_t rb = (size_t)(b * Sc + t * KT) * Dc + hoff;
        const __half* gk  = g_k  + rb;
        const __half* glk = g_lk + rb;
        const __half* gv  = g_v  + rb;
        const uint32_t ksb = smb + (uint32_t)(KS_H + s * KSBUF) * 2;
        const uint32_t vsb = smb + (uint32_t)(VS_H + s * VSBUF) * 2;
#pragma unroll
        for (int i = 0; i < 2; i++) {
            int id = tid + i * 256;
            int row = id >> 4, ch = id & 15;
            const __half* src = (ch < 8) ? (gk + (size_t)row * Dc + ch * 8)
                                         : (glk + (size_t)row * Dc + (ch - 8) * 8);
            cpa16(ksb + (uint32_t)(row * KSTR + ch * 8) * 2, src);
        }
        {
            int row = tid >> 3, ch = tid & 7;
            cpa16(vsb + (uint32_t)(row * VSTR + ch * 8) * 2, gv + (size_t)row * Dc + ch * 8);
        }
        if (tid < 8)
            cpa16(smb + (uint32_t)MS_B + (uint32_t)(s * KT + tid * 4) * 4,
                  g_mkl + (size_t)b * Sc + t * KT + tid * 4);
        CPA_COMMIT();
    };

    // ---- Q staging (separate region, survives whole kernel)
    {
        const size_t rb = (size_t)(b * Sc + q0) * Dc + hoff;
#pragma unroll
        for (int i = 0; i < 16; i++) {
            int id = tid + i * 256;
            int row = id >> 4, ch = id & 15;
            const __half* src = (ch < 8) ? (g_q + rb + (size_t)row * Dc + ch * 8)
                                         : (g_lq + rb + (size_t)row * Dc + (ch - 8) * 8);
            cpa16(smb + (uint32_t)QS_B + (uint32_t)(row * KSTR + ch * 8) * 2, src);
        }
        CPA_COMMIT();
    }
    // ones-column init: V dims 64-71 = {1,0,...} in all 4 ring bufs (never
    // overwritten: cp.async only touches dims 0-63). 4 bufs x 32 keys = 128.
    if (tid < 128) {
        int buf = tid >> 5, key = tid & 31;
        uint4* p = (uint4*)((char*)smh +
            ((size_t)(VS_H + buf * VSBUF + key * VSTR + 64) * 2));
        *p = make_uint4(0x00003C00u, 0u, 0u, 0u);
    }
    issue_tile(0);

    // ---- Q fragments -> registers (32 rows/warp: two 16-row frags per kc)
    CPA_WAIT(1);            // Q-staging group complete (tile0 may be in flight)
    __syncthreads();
    uint32_t qa[8][2][4];
    {
        const uint32_t qlane = smb + (uint32_t)QS_B +
            ((uint32_t)((wid * 32 + (lane & 15)) * KSTR + ((lane >> 4) << 3)) << 1);
#pragma unroll
        for (int kc = 0; kc < 8; kc++) {
            ldsm4(qa[kc][0][0], qa[kc][0][1], qa[kc][0][2], qa[kc][0][3],
                  qlane + ((uint32_t)(kc * 16) << 1));
            ldsm4(qa[kc][1][0], qa[kc][1][1], qa[kc][1][2], qa[kc][1][3],
                  qlane + ((uint32_t)(16 * KSTR + kc * 16) << 1));
        }
    }

    float oacc[2][8][4];
    float oacc2[2][4];
    uint32_t pold[2][2][4];   // [kb][mt][4]
#pragma unroll
    for (int mt = 0; mt < 2; mt++) {
#pragma unroll
        for (int nt = 0; nt < 8; nt++)
#pragma unroll
            for (int c = 0; c < 4; c++) oacc[mt][nt][c] = 0.0f;
#pragma unroll
        for (int c = 0; c < 4; c++) oacc2[mt][c] = 0.0f;
#pragma unroll
        for (int kb = 0; kb < 2; kb++)
#pragma unroll
            for (int c = 0; c < 4; c++) pold[kb][mt][c] = 0u;
    }

    const uint32_t k_loff = ((uint32_t)(lane & 15) * KSTR + ((lane >> 4) << 3)) << 1;
    const uint32_t v_loff = ((uint32_t)((lane & 7) + (((lane >> 3) & 1) << 3)) * VSTR
                             + ((lane >> 4) << 3)) << 1;
    const uint32_t v2_loff = ((uint32_t)(lane & 15) * VSTR + 64) << 1;
    const float C1 = 0.18033688011112042f;   // 0.125 * log2(e)

    for (int t = 0; t < NT; t++) {
        if (t < NT - 1) { issue_tile(t + 1); CPA_WAIT(1); }
        else            { CPA_WAIT(0); }
        __syncthreads();

        const int s = t & 3, sp = (t - 1) & 3;
        const uint32_t ksl  = smb + ((uint32_t)(KS_H + s * KSBUF) << 1) + k_loff;
        const uint32_t vsl  = smb + ((uint32_t)(VS_H + sp * VSBUF) << 1) + v_loff;
        const uint32_t vsl2 = smb + ((uint32_t)(VS_H + sp * VSBUF) << 1) + v2_loff;
        const float* ms = msf + s * KT;

        // ---- QK(t): 32q x 32k x 128d  (64 mma16, 16 ldsm4)
        float sacc[2][4][4];
#pragma unroll
        for (int mt = 0; mt < 2; mt++)
#pragma unroll
            for (int nt = 0; nt < 4; nt++)
#pragma unroll
                for (int c = 0; c < 4; c++) sacc[mt][nt][c] = 0.0f;

#pragma unroll
        for (int kc = 0; kc < 8; kc++) {
#pragma unroll
            for (int nt2 = 0; nt2 < 2; nt2++) {
                uint32_t m0r, m1r, m2r, m3r;
                ldsm4(m0r, m1r, m2r, m3r,
                      ksl + ((uint32_t)(nt2 * 16 * KSTR + kc * 16) << 1));
                uint32_t b0[2] = {m0r, m2r}, b1[2] = {m1r, m3r};
#pragma unroll
                for (int mt = 0; mt < 2; mt++) {
                    mma16(sacc[mt][2 * nt2],     qa[kc][mt], b0);
                    mma16(sacc[mt][2 * nt2 + 1], qa[kc][mt], b1);
                }
            }
        }

        // ---- PV(t-1): O += P @ V (V frags shared across both row-halves)
        if (t > 0) {
#pragma unroll
            for (int kb = 0; kb < 2; kb++) {
#pragma unroll
                for (int nt2 = 0; nt2 < 4; nt2++) {
                    uint32_t m0r, m1r, m2r, m3r;
                    ldsm4t(m0r, m1r, m2r, m3r,
                           vsl + ((uint32_t)(kb * 16 * VSTR + nt2 * 16) << 1));
                    uint32_t b0[2] = {m0r, m1r}, b1[2] = {m2r, m3r};
#pragma unroll
                    for (int mt = 0; mt < 2; mt++) {
                        mma16(oacc[mt][2 * nt2],     pold[kb][mt], b0);
                        mma16(oacc[mt][2 * nt2 + 1], pold[kb][mt], b1);
                    }
                }
                uint32_t e0, e1;
                ldsm2t(e0, e1, vsl2 + ((uint32_t)(kb * 16 * VSTR) << 1));
                uint32_t be[2] = {e0, e1};
#pragma unroll
                for (int mt = 0; mt < 2; mt++)
                    mma16(oacc2[mt], pold[kb][mt], be);
            }
        }

        // ---- softmax(t): fixed shift, straight-line (EX2 via inline PTX)
#pragma unroll
        for (int mt = 0; mt < 2; mt++)
#pragma unroll
            for (int nt = 0; nt < 4; nt++) {
                const float mk0 = ms[nt * 8 + 2 * tig], mk1 = ms[nt * 8 + 2 * tig + 1];
                sacc[mt][nt][0] = ex2(sacc[mt][nt][0] * C1 + mk0);
                sacc[mt][nt][1] = ex2(sacc[mt][nt][1] * C1 + mk1);
                sacc[mt][nt][2] = ex2(sacc[mt][nt][2] * C1 + mk0);
                sacc[mt][nt][3] = ex2(sacc[mt][nt][3] * C1 + mk1);
            }
#pragma unroll
        for (int kb = 0; kb < 2; kb++)
#pragma unroll
            for (int mt = 0; mt < 2; mt++) {
                pold[kb][mt][0] = h2pack(sacc[mt][2 * kb][0],     sacc[mt][2 * kb][1]);
                pold[kb][mt][1] = h2pack(sacc[mt][2 * kb][2],     sacc[mt][2 * kb][3]);
                pold[kb][mt][2] = h2pack(sacc[mt][2 * kb + 1][0], sacc[mt][2 * kb + 1][1]);
                pold[kb][mt][3] = h2pack(sacc[mt][2 * kb + 1][2], sacc[mt][2 * kb + 1][3]);
            }
    }

    // ---- drain: PV(NT-1)
    {
        const int sp = (NT - 1) & 3;
        const uint32_t vsl  = smb + ((uint32_t)(VS_H + sp * VSBUF) << 1) + v_loff;
        const uint32_t vsl2 = smb + ((uint32_t)(VS_H + sp * VSBUF) << 1) + v2_loff;
#pragma unroll
        for (int kb = 0; kb < 2; kb++) {
#pragma unroll
            for (int nt2 = 0; nt2 < 4; nt2++) {
                uint32_t m0r, m1r, m2r, m3r;
                ldsm4t(m0r, m1r, m2r, m3r,
                       vsl + ((uint32_t)(kb * 16 * VSTR + nt2 * 16) << 1));
                uint32_t b0[2] = {m0r, m1r}, b1[2] = {m2r, m3r};
#pragma unroll
                for (int mt = 0; mt < 2; mt++) {
                    mma16(oacc[mt][2 * nt2],     pold[kb][mt], b0);
                    mma16(oacc[mt][2 * nt2 + 1], pold[kb][mt], b1);
                }
            }
            uint32_t e0, e1;
            ldsm2t(e0, e1, vsl2 + ((uint32_t)(kb * 16 * VSTR) << 1));
            uint32_t be[2] = {e0, e1};
#pragma unroll
            for (int mt = 0; mt < 2; mt++)
                mma16(oacc2[mt], pold[kb][mt], be);
        }
    }

    // ---- epilogue: l in ones-column (col 64 lives in tig==0 lanes d[0]/d[2])
#pragma unroll
    for (int mt = 0; mt < 2; mt++) {
        const float l0 = __shfl_sync(0xffffffffu, oacc2[mt][0], lane & ~3);
        const float l1 = __shfl_sync(0xffffffffu, oacc2[mt][2], lane & ~3);
        const float i0 = 1.0f / l0, i1 = 1.0f / l1;
        const int row = b * Sc + q0 + wid * 32 + mt * 16 + g;
        float* ob = out + (size_t)row * Dc + hoff;
#pragma unroll
        for (int nt = 0; nt < 8; nt++) {
            const int col = nt * 8 + 2 * tig;
            *(float2*)&ob[col] = make_float2(oacc[mt][nt][0] * i0, oacc[mt][nt][1] * i0);
            *(float2*)&ob[(size_t)8 * Dc + col] =
                make_float2(oacc[mt][nt][2] * i1, oacc[mt][nt][3] * i1);
        }
    }
}

// ----------------------------------------------------------------------------
// Launch
// ----------------------------------------------------------------------------
extern "C" void kernel_launch(void* const* d_in, const int* in_sizes, int n_in,
                              void* d_out, int out_size)
{
    const float* hs   = (const float*)d_in[0];
    const float* lq   = (const float*)d_in[1];
    const float* lk   = (const float*)d_in[2];
    const float* mask = (const float*)d_in[3];
    const float* Wq   = (const float*)d_in[4];
    const float* bq   = (const float*)d_in[5];
    const float* Wk   = (const float*)d_in[6];
    const float* bk   = (const float*)d_in[7];
    const float* Wv   = (const float*)d_in[8];
    const float* bv   = (const float*)d_in[9];
    float* out = (float*)d_out;

    // Stage A prep: hs + weights only (linear inputs)
    dim3 gp(512, 4);
    prep_a<<<gp, 256>>>(hs, Wq, Wk, Wv);

    // Linears + overlapped stage-B prep (lq/lk/mask) as grid.z == 3
    cudaFuncSetAttribute(linear_tc, cudaFuncAttributeMaxDynamicSharedMemorySize, LIN_SMEM);
    dim3 gl(Dc / 128, Mrows / 128, 4);   // (6, 64, 4): z=0..2 GEMM, z=3 prep-B
    linear_tc<<<gl, 256, LIN_SMEM>>>(bq, bk, bv, lq, lk, mask);

    cudaFuncSetAttribute(attn_tc, cudaFuncAttributeMaxDynamicSharedMemorySize, ATT_SMEM);
    dim3 ga(Sc / 256, Hc, Bc);           // (8, 12, 4) = 384 CTAs
    attn_tc<<<ga, 256, ATT_SMEM>>>(out);
}

// round 16
// speedup vs baseline: 1.0703x; 1.0703x over previous
#include <cuda_runtime.h>
#include <cuda_fp16.h>
#include <cstdint>

// ----------------------------------------------------------------------------
// Problem constants
// ----------------------------------------------------------------------------
#define Bc   4
#define Sc   2048
#define Dc   768
#define Hc   12
#define HDc  64
#define Mrows (Bc * Sc)   // 8192

// Scratch (device globals)
__device__ __half g_q [(size_t)Mrows * Dc];
__device__ __half g_k [(size_t)Mrows * Dc];
__device__ __half g_v [(size_t)Mrows * Dc];
__device__ __half g_hs[(size_t)Mrows * Dc];
__device__ __half g_lq[(size_t)Mrows * Dc];
__device__ __half g_lk[(size_t)Mrows * Dc];
__device__ __half g_wq[(size_t)Dc * Dc];
__device__ __half g_wk[(size_t)Dc * Dc];
__device__ __half g_wv[(size_t)Dc * Dc];
__device__ float  g_mkl[(size_t)Bc * Sc];   // mask * log2(e) - 8

// ----------------------------------------------------------------------------
// Helpers
// ----------------------------------------------------------------------------
__device__ __forceinline__ uint32_t smem_u32(const void* p) {
    uint32_t a;
    asm("{ .reg .u64 t; cvta.to.shared.u64 t, %1; cvt.u32.u64 %0, t; }" : "=r"(a) : "l"(p));
    return a;
}
__device__ __forceinline__ void cpa16(uint32_t dst, const void* src) {
    asm volatile("cp.async.cg.shared.global [%0], [%1], 16;" :: "r"(dst), "l"(src));
}
#define CPA_COMMIT() asm volatile("cp.async.commit_group;" ::: "memory")
#define CPA_WAIT(N)  asm volatile("cp.async.wait_group %0;" :: "n"(N) : "memory")

__device__ __forceinline__ float ex2(float x) {
    float r;
    asm("ex2.approx.f32 %0, %1;" : "=f"(r) : "f"(x));
    return r;
}

__device__ __forceinline__ void ldsm4(uint32_t& r0, uint32_t& r1, uint32_t& r2, uint32_t& r3,
                                      uint32_t addr) {
    asm volatile("ldmatrix.sync.aligned.m8n8.x4.shared.b16 {%0,%1,%2,%3}, [%4];"
                 : "=r"(r0), "=r"(r1), "=r"(r2), "=r"(r3) : "r"(addr));
}
__device__ __forceinline__ void ldsm4t(uint32_t& r0, uint32_t& r1, uint32_t& r2, uint32_t& r3,
                                       uint32_t addr) {
    asm volatile("ldmatrix.sync.aligned.m8n8.x4.trans.shared.b16 {%0,%1,%2,%3}, [%4];"
                 : "=r"(r0), "=r"(r1), "=r"(r2), "=r"(r3) : "r"(addr));
}

// d += a @ b  (m16n8k16, fp16 inputs, f32 accum)
__device__ __forceinline__ void mma16(float* d, const uint32_t* a, const uint32_t* b) {
    asm volatile(
        "mma.sync.aligned.m16n8k16.row.col.f32.f16.f16.f32 "
        "{%0,%1,%2,%3}, {%4,%5,%6,%7}, {%8,%9}, {%0,%1,%2,%3};\n"
        : "+f"(d[0]), "+f"(d[1]), "+f"(d[2]), "+f"(d[3])
        : "r"(a[0]), "r"(a[1]), "r"(a[2]), "r"(a[3]), "r"(b[0]), "r"(b[1]));
}

__device__ __forceinline__ uint32_t h2pack(float a, float b) {
    __half2 h = __floats2half2_rn(a, b);
    return *reinterpret_cast<uint32_t*>(&h);
}

// ----------------------------------------------------------------------------
// Prep: f32 -> fp16 for six arrays; mask -> f32(mask*log2(e) - 8)
// ----------------------------------------------------------------------------
__global__ void round_all(const float* __restrict__ hs, const float* __restrict__ lq,
                          const float* __restrict__ lk, const float* __restrict__ wq,
                          const float* __restrict__ wk, const float* __restrict__ wv,
                          const float* __restrict__ mask)
{
    const int which = blockIdx.y;
    int i = blockIdx.x * blockDim.x + threadIdx.x;
    int stride = gridDim.x * blockDim.x;

    if (which == 6) {
        const float L2E = 1.4426950408889634f;
        const int n4 = (Bc * Sc) / 4;
        for (; i < n4; i += stride) {
            float4 v = ((const float4*)mask)[i];
            v.x = v.x * L2E - 8.0f; v.y = v.y * L2E - 8.0f;
            v.z = v.z * L2E - 8.0f; v.w = v.w * L2E - 8.0f;
            ((float4*)g_mkl)[i] = v;
        }
        return;
    }

    const float* s;
    __half* d;
    int n8;
    if (which == 0)      { s = hs; d = g_hs; n8 = (Mrows * Dc) / 8; }
    else if (which == 1) { s = lq; d = g_lq; n8 = (Mrows * Dc) / 8; }
    else if (which == 2) { s = lk; d = g_lk; n8 = (Mrows * Dc) / 8; }
    else if (which == 3) { s = wq; d = g_wq; n8 = (Dc * Dc) / 8; }
    else if (which == 4) { s = wk; d = g_wk; n8 = (Dc * Dc) / 8; }
    else                 { s = wv; d = g_wv; n8 = (Dc * Dc) / 8; }

    for (; i < n8; i += stride) {
        float4 v0 = ((const float4*)s)[2 * i];
        float4 v1 = ((const float4*)s)[2 * i + 1];
        uint4 o;
        o.x = h2pack(v0.x, v0.y);
        o.y = h2pack(v0.z, v0.w);
        o.z = h2pack(v1.x, v1.y);
        o.w = h2pack(v1.z, v1.w);
        ((uint4*)d)[i] = o;
    }
}

// ----------------------------------------------------------------------------
// Linear: Y = X @ W^T + b  (fp16 m16n8k16 + ldmatrix, 128x128x32)
// 3-stage cp.async pipeline, one __syncthreads per k-iter. (verified R9-R12)
// ----------------------------------------------------------------------------
#define LSTR 40
#define LIN_STAGE_H (128 * LSTR)
#define LIN_SMEM (6 * LIN_STAGE_H * 2)           // 61440 B

__global__ __launch_bounds__(256, 2) void linear_tc(
    const float* __restrict__ bq,
    const float* __restrict__ bk,
    const float* __restrict__ bv)
{
    extern __shared__ __align__(16) __half smh[];
    const uint32_t smb = smem_u32(smh);

    const int z = blockIdx.z;
    const __half* X    = g_hs;
    const __half* W    = (z == 0) ? g_wq : (z == 1) ? g_wk : g_wv;
    const float* bias  = (z == 0) ? bq   : (z == 1) ? bk   : bv;
    __half* Y          = (z == 0) ? g_q  : (z == 1) ? g_k  : g_v;

    const int tid = threadIdx.x;
    const int wid = tid >> 5, lane = tid & 31;
    const int g = lane >> 2, tig = lane & 3;
    const int warpm = wid >> 1, warpn = wid & 1;
    const int bm = blockIdx.y * 128, bn = blockIdx.x * 128;

    auto issue = [&](int it) {
        const int st = it % 3;
        const int k0 = it * 32;
        const uint32_t ab = smb + (uint32_t)(st * 2 * LIN_STAGE_H) * 2;
        const uint32_t bb = ab + (uint32_t)LIN_STAGE_H * 2;
#pragma unroll
        for (int i = 0; i < 2; i++) {
            int id = tid + i * 256;
            int row = id >> 2, ch = id & 3;
            uint32_t off = (uint32_t)(row * LSTR + ch * 8) * 2;
            cpa16(ab + off, X + (size_t)(bm + row) * Dc + k0 + ch * 8);
            cpa16(bb + off, W + (size_t)(bn + row) * Dc + k0 + ch * 8);
        }
        CPA_COMMIT();
    };

    float acc[2][8][4];
#pragma unroll
    for (int mt = 0; mt < 2; mt++)
#pragma unroll
        for (int nt = 0; nt < 8; nt++)
#pragma unroll
            for (int c = 0; c < 4; c++) acc[mt][nt][c] = 0.0f;

    const uint32_t a_loff = ((uint32_t)(warpm * 32 + (lane & 15)) * LSTR + ((lane >> 4) << 3)) * 2;
    const uint32_t b_loff = ((uint32_t)(warpn * 64 + (lane & 15)) * LSTR + ((lane >> 4) << 3)) * 2;

    issue(0);
    issue(1);
    for (int it = 0; it < 24; it++) {
        if (it == 23) { CPA_WAIT(0); } else { CPA_WAIT(1); }
        __syncthreads();
        if (it < 22) issue(it + 2);

        const int st = it % 3;
        const uint32_t ab = smb + (uint32_t)(st * 2 * LIN_STAGE_H) * 2 + a_loff;
        const uint32_t bb = smb + (uint32_t)(st * 2 * LIN_STAGE_H + LIN_STAGE_H) * 2 + b_loff;

#pragma unroll
        for (int kc = 0; kc < 2; kc++) {
            uint32_t afr[2][4];
#pragma unroll
            for (int mt = 0; mt < 2; mt++)
                ldsm4(afr[mt][0], afr[mt][1], afr[mt][2], afr[mt][3],
                      ab + ((uint32_t)(mt * 16 * LSTR + kc * 16) << 1));
#pragma unroll
            for (int ntp = 0; ntp < 4; ntp++) {
                uint32_t m0, m1, m2, m3;
                ldsm4(m0, m1, m2, m3, bb + ((uint32_t)(ntp * 16 * LSTR + kc * 16) << 1));
                uint32_t b0[2] = {m0, m2}, b1[2] = {m1, m3};
#pragma unroll
                for (int mt = 0; mt < 2; mt++) {
                    mma16(acc[mt][2 * ntp],     afr[mt], b0);
                    mma16(acc[mt][2 * ntp + 1], afr[mt], b1);
                }
            }
        }
    }

#pragma unroll
    for (int mt = 0; mt < 2; mt++) {
        const int row0 = bm + warpm * 32 + mt * 16 + g;
#pragma unroll
        for (int nt = 0; nt < 8; nt++) {
            const int col = bn + warpn * 64 + nt * 8 + 2 * tig;
            const float bx = bias[col], by = bias[col + 1];
            *(uint32_t*)&Y[(size_t)row0 * Dc + col] =
                h2pack(acc[mt][nt][0] + bx, acc[mt][nt][1] + by);
            *(uint32_t*)&Y[(size_t)(row0 + 8) * Dc + col] =
                h2pack(acc[mt][nt][2] + bx, acc[mt][nt][3] + by);
        }
    }
}

// ----------------------------------------------------------------------------
// Flash attention (fp16 m16n8k16): fixed-shift f32 softmax; l via per-lane
// partial sums (quad-reduced ONCE in epilogue, no in-loop cross-lane ops,
// no ones-column MMAs). 32 q-rows/warp, CTA = (b, h, 256-q), KT=32, occ 1.
// ----------------------------------------------------------------------------
#define KT 32
#define NT 64                           // Sc / KT
#define KSTR 136
#define VSTR 72
#define KSBUF (KT * KSTR)               // 4352 halfs
#define VSBUF (KT * VSTR)               // 2304 halfs
#define KS_H 0                          // 4 bufs
#define VS_H (4 * KSBUF)                // 17408
#define MS_B ((VS_H + 4 * VSBUF) * 2)   // 53248 bytes
#define QS_B (MS_B + 4 * KT * 4)        // 53760 bytes (Q staging region)
#define ATT_SMEM (QS_B + 256 * KSTR * 2)  // 123392 B

__global__ __launch_bounds__(256, 1) void attn_tc(
    float* __restrict__ out)
{
    extern __shared__ __align__(16) __half smh[];
    const uint32_t smb = smem_u32(smh);
    float* msf = (float*)((char*)smh + MS_B);

    const int tid = threadIdx.x;
    const int wid = tid >> 5, lane = tid & 31;
    const int g = lane >> 2, tig = lane & 3;

    const int b = blockIdx.z, h = blockIdx.y, q0 = blockIdx.x * 256;
    const int hoff = h * HDc;

    auto issue_tile = [&](int t) {
        const int s = t & 3;
        const size_t rb = (size_t)(b * Sc + t * KT) * Dc + hoff;
        const __half* gk  = g_k  + rb;
        const __half* glk = g_lk + rb;
        const __half* gv  = g_v  + rb;
        const uint32_t ksb = smb + (uint32_t)(KS_H + s * KSBUF) * 2;
        const uint32_t vsb = smb + (uint32_t)(VS_H + s * VSBUF) * 2;
#pragma unroll
        for (int i = 0; i < 2; i++) {
            int id = tid + i * 256;
            int row = id >> 4, ch = id & 15;
            const __half* src = (ch < 8) ? (gk + (size_t)row * Dc + ch * 8)
                                         : (glk + (size_t)row * Dc + (ch - 8) * 8);
            cpa16(ksb + (uint32_t)(row * KSTR + ch * 8) * 2, src);
        }
        {
            int row = tid >> 3, ch = tid & 7;
            cpa16(vsb + (uint32_t)(row * VSTR + ch * 8) * 2, gv + (size_t)row * Dc + ch * 8);
        }
        if (tid < 8)
            cpa16(smb + (uint32_t)MS_B + (uint32_t)(s * KT + tid * 4) * 4,
                  g_mkl + (size_t)b * Sc + t * KT + tid * 4);
        CPA_COMMIT();
    };

    // ---- Q staging (separate region, survives whole kernel)
    {
        const size_t rb = (size_t)(b * Sc + q0) * Dc + hoff;
#pragma unroll
        for (int i = 0; i < 16; i++) {
            int id = tid + i * 256;
            int row = id >> 4, ch = id & 15;
            const __half* src = (ch < 8) ? (g_q + rb + (size_t)row * Dc + ch * 8)
                                         : (g_lq + rb + (size_t)row * Dc + (ch - 8) * 8);
            cpa16(smb + (uint32_t)QS_B + (uint32_t)(row * KSTR + ch * 8) * 2, src);
        }
        CPA_COMMIT();
    }
    issue_tile(0);

    // ---- Q fragments -> registers (32 rows/warp: two 16-row frags per kc)
    CPA_WAIT(1);            // Q-staging group complete (tile0 may be in flight)
    __syncthreads();
    uint32_t qa[8][2][4];
    {
        const uint32_t qlane = smb + (uint32_t)QS_B +
            ((uint32_t)((wid * 32 + (lane & 15)) * KSTR + ((lane >> 4) << 3)) << 1);
#pragma unroll
        for (int kc = 0; kc < 8; kc++) {
            ldsm4(qa[kc][0][0], qa[kc][0][1], qa[kc][0][2], qa[kc][0][3],
                  qlane + ((uint32_t)(kc * 16) << 1));
            ldsm4(qa[kc][1][0], qa[kc][1][1], qa[kc][1][2], qa[kc][1][3],
                  qlane + ((uint32_t)(16 * KSTR + kc * 16) << 1));
        }
    }

    float oacc[2][8][4];
    float l_part[2][2];       // per-lane partial sums: [mt][row-half g / g+8]
    uint32_t pold[2][2][4];   // [kb][mt][4]
#pragma unroll
    for (int mt = 0; mt < 2; mt++) {
#pragma unroll
        for (int nt = 0; nt < 8; nt++)
#pragma unroll
            for (int c = 0; c < 4; c++) oacc[mt][nt][c] = 0.0f;
        l_part[mt][0] = 0.0f; l_part[mt][1] = 0.0f;
#pragma unroll
        for (int kb = 0; kb < 2; kb++)
#pragma unroll
            for (int c = 0; c < 4; c++) pold[kb][mt][c] = 0u;
    }

    const uint32_t k_loff = ((uint32_t)(lane & 15) * KSTR + ((lane >> 4) << 3)) << 1;
    const uint32_t v_loff = ((uint32_t)((lane & 7) + (((lane >> 3) & 1) << 3)) * VSTR
                             + ((lane >> 4) << 3)) << 1;
    const float C1 = 0.18033688011112042f;   // 0.125 * log2(e)

    for (int t = 0; t < NT; t++) {
        if (t < NT - 1) { issue_tile(t + 1); CPA_WAIT(1); }
        else            { CPA_WAIT(0); }
        __syncthreads();

        const int s = t & 3, sp = (t - 1) & 3;
        const uint32_t ksl = smb + ((uint32_t)(KS_H + s * KSBUF) << 1) + k_loff;
        const uint32_t vsl = smb + ((uint32_t)(VS_H + sp * VSBUF) << 1) + v_loff;
        const float* ms = msf + s * KT;

        // ---- QK(t): 32q x 32k x 128d  (64 mma16, 16 ldsm4)
        float sacc[2][4][4];
#pragma unroll
        for (int mt = 0; mt < 2; mt++)
#pragma unroll
            for (int nt = 0; nt < 4; nt++)
#pragma unroll
                for (int c = 0; c < 4; c++) sacc[mt][nt][c] = 0.0f;

#pragma unroll
        for (int kc = 0; kc < 8; kc++) {
#pragma unroll
            for (int nt2 = 0; nt2 < 2; nt2++) {
                uint32_t m0r, m1r, m2r, m3r;
                ldsm4(m0r, m1r, m2r, m3r,
                      ksl + ((uint32_t)(nt2 * 16 * KSTR + kc * 16) << 1));
                uint32_t b0[2] = {m0r, m2r}, b1[2] = {m1r, m3r};
#pragma unroll
                for (int mt = 0; mt < 2; mt++) {
                    mma16(sacc[mt][2 * nt2],     qa[kc][mt], b0);
                    mma16(sacc[mt][2 * nt2 + 1], qa[kc][mt], b1);
                }
            }
        }

        // ---- PV(t-1): O += P @ V  (pure 64-dim, no ones-column)
        if (t > 0) {
#pragma unroll
            for (int kb = 0; kb < 2; kb++) {
#pragma unroll
                for (int nt2 = 0; nt2 < 4; nt2++) {
                    uint32_t m0r, m1r, m2r, m3r;
                    ldsm4t(m0r, m1r, m2r, m3r,
                           vsl + ((uint32_t)(kb * 16 * VSTR + nt2 * 16) << 1));
                    uint32_t b0[2] = {m0r, m1r}, b1[2] = {m2r, m3r};
#pragma unroll
                    for (int mt = 0; mt < 2; mt++) {
                        mma16(oacc[mt][2 * nt2],     pold[kb][mt], b0);
                        mma16(oacc[mt][2 * nt2 + 1], pold[kb][mt], b1);
                    }
                }
            }
        }

        // ---- softmax(t): fixed shift, f32 EX2; per-lane partial l sums only
#pragma unroll
        for (int mt = 0; mt < 2; mt++) {
            float s0 = 0.0f, s1 = 0.0f;
#pragma unroll
            for (int nt = 0; nt < 4; nt++) {
                const float mk0 = ms[nt * 8 + 2 * tig], mk1 = ms[nt * 8 + 2 * tig + 1];
                sacc[mt][nt][0] = ex2(sacc[mt][nt][0] * C1 + mk0);
                sacc[mt][nt][1] = ex2(sacc[mt][nt][1] * C1 + mk1);
                sacc[mt][nt][2] = ex2(sacc[mt][nt][2] * C1 + mk0);
                sacc[mt][nt][3] = ex2(sacc[mt][nt][3] * C1 + mk1);
                s0 += sacc[mt][nt][0] + sacc[mt][nt][1];
                s1 += sacc[mt][nt][2] + sacc[mt][nt][3];
            }
            l_part[mt][0] += s0;
            l_part[mt][1] += s1;
        }
#pragma unroll
        for (int kb = 0; kb < 2; kb++)
#pragma unroll
            for (int mt = 0; mt < 2; mt++) {
                pold[kb][mt][0] = h2pack(sacc[mt][2 * kb][0],     sacc[mt][2 * kb][1]);
                pold[kb][mt][1] = h2pack(sacc[mt][2 * kb][2],     sacc[mt][2 * kb][3]);
                pold[kb][mt][2] = h2pack(sacc[mt][2 * kb + 1][0], sacc[mt][2 * kb + 1][1]);
                pold[kb][mt][3] = h2pack(sacc[mt][2 * kb + 1][2], sacc[mt][2 * kb + 1][3]);
            }
    }

    // ---- drain: PV(NT-1)
    {
        const int sp = (NT - 1) & 3;
        const uint32_t vsl = smb + ((uint32_t)(VS_H + sp * VSBUF) << 1) + v_loff;
#pragma unroll
        for (int kb = 0; kb < 2; kb++) {
#pragma unroll
            for (int nt2 = 0; nt2 < 4; nt2++) {
                uint32_t m0r, m1r, m2r, m3r;
                ldsm4t(m0r, m1r, m2r, m3r,
                       vsl + ((uint32_t)(kb * 16 * VSTR + nt2 * 16) << 1));
                uint32_t b0[2] = {m0r, m1r}, b1[2] = {m2r, m3r};
#pragma unroll
                for (int mt = 0; mt < 2; mt++) {
                    mma16(oacc[mt][2 * nt2],     pold[kb][mt], b0);
                    mma16(oacc[mt][2 * nt2 + 1], pold[kb][mt], b1);
                }
            }
        }
    }

    // ---- epilogue: ONE quad reduction for l, then normalize + store
#pragma unroll
    for (int mt = 0; mt < 2; mt++) {
        float l0 = l_part[mt][0], l1 = l_part[mt][1];
        l0 += __shfl_xor_sync(0xffffffffu, l0, 1);
        l0 += __shfl_xor_sync(0xffffffffu, l0, 2);
        l1 += __shfl_xor_sync(0xffffffffu, l1, 1);
        l1 += __shfl_xor_sync(0xffffffffu, l1, 2);
        const float i0 = 1.0f / l0, i1 = 1.0f / l1;
        const int row = b * Sc + q0 + wid * 32 + mt * 16 + g;
        float* ob = out + (size_t)row * Dc + hoff;
#pragma unroll
        for (int nt = 0; nt < 8; nt++) {
            const int col = nt * 8 + 2 * tig;
            *(float2*)&ob[col] = make_float2(oacc[mt][nt][0] * i0, oacc[mt][nt][1] * i0);
            *(float2*)&ob[(size_t)8 * Dc + col] =
                make_float2(oacc[mt][nt][2] * i1, oacc[mt][nt][3] * i1);
        }
    }
}

// ----------------------------------------------------------------------------
// Launch  (R12 structure: serial prep, 3-z linear, attention)
// ----------------------------------------------------------------------------
extern "C" void kernel_launch(void* const* d_in, const int* in_sizes, int n_in,
                              void* d_out, int out_size)
{
    const float* hs   = (const float*)d_in[0];
    const float* lq   = (const float*)d_in[1];
    const float* lk   = (const float*)d_in[2];
    const float* mask = (const float*)d_in[3];
    const float* Wq   = (const float*)d_in[4];
    const float* bq   = (const float*)d_in[5];
    const float* Wk   = (const float*)d_in[6];
    const float* bk   = (const float*)d_in[7];
    const float* Wv   = (const float*)d_in[8];
    const float* bv   = (const float*)d_in[9];
    float* out = (float*)d_out;

    dim3 gp(512, 7);
    round_all<<<gp, 256>>>(hs, lq, lk, Wq, Wk, Wv, mask);

    cudaFuncSetAttribute(linear_tc, cudaFuncAttributeMaxDynamicSharedMemorySize, LIN_SMEM);
    dim3 gl(Dc / 128, Mrows / 128, 3);   // (6, 64, 3)
    linear_tc<<<gl, 256, LIN_SMEM>>>(bq, bk, bv);

    cudaFuncSetAttribute(attn_tc, cudaFuncAttributeMaxDynamicSharedMemorySize, ATT_SMEM);
    dim3 ga(Sc / 256, Hc, Bc);           // (8, 12, 4) = 384 CTAs
    attn_tc<<<ga, 256, ATT_SMEM>>>(out);
}

// round 17
// speedup vs baseline: 1.0789x; 1.0080x over previous
#include <cuda_runtime.h>
#include <cuda_fp16.h>
#include <cstdint>

// ----------------------------------------------------------------------------
// Problem constants
// ----------------------------------------------------------------------------
#define Bc   4
#define Sc   2048
#define Dc   768
#define Hc   12
#define HDc  64
#define Mrows (Bc * Sc)   // 8192

// Scratch (device globals)
__device__ __half g_q [(size_t)Mrows * Dc];
__device__ __half g_k [(size_t)Mrows * Dc];
__device__ __half g_v [(size_t)Mrows * Dc];
__device__ __half g_hs[(size_t)Mrows * Dc];
__device__ __half g_lk[(size_t)Mrows * Dc];
__device__ __half g_wq[(size_t)Dc * Dc];
__device__ __half g_wk[(size_t)Dc * Dc];
__device__ __half g_wv[(size_t)Dc * Dc];
__device__ float  g_mkl[(size_t)Bc * Sc];   // mask * log2(e) - 8

// ----------------------------------------------------------------------------
// Helpers
// ----------------------------------------------------------------------------
__device__ __forceinline__ uint32_t smem_u32(const void* p) {
    uint32_t a;
    asm("{ .reg .u64 t; cvta.to.shared.u64 t, %1; cvt.u32.u64 %0, t; }" : "=r"(a) : "l"(p));
    return a;
}
__device__ __forceinline__ void cpa16(uint32_t dst, const void* src) {
    asm volatile("cp.async.cg.shared.global [%0], [%1], 16;" :: "r"(dst), "l"(src));
}
#define CPA_COMMIT() asm volatile("cp.async.commit_group;" ::: "memory")
#define CPA_WAIT(N)  asm volatile("cp.async.wait_group %0;" :: "n"(N) : "memory")

__device__ __forceinline__ float ex2(float x) {
    float r;
    asm("ex2.approx.f32 %0, %1;" : "=f"(r) : "f"(x));
    return r;
}

__device__ __forceinline__ void ldsm4(uint32_t& r0, uint32_t& r1, uint32_t& r2, uint32_t& r3,
                                      uint32_t addr) {
    asm volatile("ldmatrix.sync.aligned.m8n8.x4.shared.b16 {%0,%1,%2,%3}, [%4];"
                 : "=r"(r0), "=r"(r1), "=r"(r2), "=r"(r3) : "r"(addr));
}
__device__ __forceinline__ void ldsm4t(uint32_t& r0, uint32_t& r1, uint32_t& r2, uint32_t& r3,
                                       uint32_t addr) {
    asm volatile("ldmatrix.sync.aligned.m8n8.x4.trans.shared.b16 {%0,%1,%2,%3}, [%4];"
                 : "=r"(r0), "=r"(r1), "=r"(r2), "=r"(r3) : "r"(addr));
}

// d += a @ b  (m16n8k16, fp16 inputs, f32 accum)
__device__ __forceinline__ void mma16(float* d, const uint32_t* a, const uint32_t* b) {
    asm volatile(
        "mma.sync.aligned.m16n8k16.row.col.f32.f16.f16.f32 "
        "{%0,%1,%2,%3}, {%4,%5,%6,%7}, {%8,%9}, {%0,%1,%2,%3};\n"
        : "+f"(d[0]), "+f"(d[1]), "+f"(d[2]), "+f"(d[3])
        : "r"(a[0]), "r"(a[1]), "r"(a[2]), "r"(a[3]), "r"(b[0]), "r"(b[1]));
}

__device__ __forceinline__ uint32_t h2pack(float a, float b) {
    __half2 h = __floats2half2_rn(a, b);
    return *reinterpret_cast<uint32_t*>(&h);
}

// ----------------------------------------------------------------------------
// Prep: f32 -> fp16 for hs/lk/weights; mask -> f32(mask*log2(e) - 8)
// (lq conversion moved into the attention prologue)
// ----------------------------------------------------------------------------
__global__ void round_all(const float* __restrict__ hs, const float* __restrict__ lk,
                          const float* __restrict__ wq, const float* __restrict__ wk,
                          const float* __restrict__ wv, const float* __restrict__ mask)
{
    const int which = blockIdx.y;
    int i = blockIdx.x * blockDim.x + threadIdx.x;
    int stride = gridDim.x * blockDim.x;

    if (which == 5) {
        const float L2E = 1.4426950408889634f;
        const int n4 = (Bc * Sc) / 4;
        for (; i < n4; i += stride) {
            float4 v = ((const float4*)mask)[i];
            v.x = v.x * L2E - 8.0f; v.y = v.y * L2E - 8.0f;
            v.z = v.z * L2E - 8.0f; v.w = v.w * L2E - 8.0f;
            ((float4*)g_mkl)[i] = v;
        }
        return;
    }

    const float* s;
    __half* d;
    int n8;
    if (which == 0)      { s = hs; d = g_hs; n8 = (Mrows * Dc) / 8; }
    else if (which == 1) { s = lk; d = g_lk; n8 = (Mrows * Dc) / 8; }
    else if (which == 2) { s = wq; d = g_wq; n8 = (Dc * Dc) / 8; }
    else if (which == 3) { s = wk; d = g_wk; n8 = (Dc * Dc) / 8; }
    else                 { s = wv; d = g_wv; n8 = (Dc * Dc) / 8; }

    for (; i < n8; i += stride) {
        float4 v0 = ((const float4*)s)[2 * i];
        float4 v1 = ((const float4*)s)[2 * i + 1];
        uint4 o;
        o.x = h2pack(v0.x, v0.y);
        o.y = h2pack(v0.z, v0.w);
        o.z = h2pack(v1.x, v1.y);
        o.w = h2pack(v1.z, v1.w);
        ((uint4*)d)[i] = o;
    }
}

// ----------------------------------------------------------------------------
// Linear: Y = X @ W^T + b  (fp16 m16n8k16 + ldmatrix, 128x128x32)
// 3-stage cp.async pipeline, one __syncthreads per k-iter. (verified R9-R16)
// ----------------------------------------------------------------------------
#define LSTR 40
#define LIN_STAGE_H (128 * LSTR)
#define LIN_SMEM (6 * LIN_STAGE_H * 2)           // 61440 B

__global__ __launch_bounds__(256, 2) void linear_tc(
    const float* __restrict__ bq,
    const float* __restrict__ bk,
    const float* __restrict__ bv)
{
    extern __shared__ __align__(16) __half smh[];
    const uint32_t smb = smem_u32(smh);

    const int z = blockIdx.z;
    const __half* X    = g_hs;
    const __half* W    = (z == 0) ? g_wq : (z == 1) ? g_wk : g_wv;
    const float* bias  = (z == 0) ? bq   : (z == 1) ? bk   : bv;
    __half* Y          = (z == 0) ? g_q  : (z == 1) ? g_k  : g_v;

    const int tid = threadIdx.x;
    const int wid = tid >> 5, lane = tid & 31;
    const int g = lane >> 2, tig = lane & 3;
    const int warpm = wid >> 1, warpn = wid & 1;
    const int bm = blockIdx.y * 128, bn = blockIdx.x * 128;

    auto issue = [&](int it) {
        const int st = it % 3;
        const int k0 = it * 32;
        const uint32_t ab = smb + (uint32_t)(st * 2 * LIN_STAGE_H) * 2;
        const uint32_t bb = ab + (uint32_t)LIN_STAGE_H * 2;
#pragma unroll
        for (int i = 0; i < 2; i++) {
            int id = tid + i * 256;
            int row = id >> 2, ch = id & 3;
            uint32_t off = (uint32_t)(row * LSTR + ch * 8) * 2;
            cpa16(ab + off, X + (size_t)(bm + row) * Dc + k0 + ch * 8);
            cpa16(bb + off, W + (size_t)(bn + row) * Dc + k0 + ch * 8);
        }
        CPA_COMMIT();
    };

    float acc[2][8][4];
#pragma unroll
    for (int mt = 0; mt < 2; mt++)
#pragma unroll
        for (int nt = 0; nt < 8; nt++)
#pragma unroll
            for (int c = 0; c < 4; c++) acc[mt][nt][c] = 0.0f;

    const uint32_t a_loff = ((uint32_t)(warpm * 32 + (lane & 15)) * LSTR + ((lane >> 4) << 3)) * 2;
    const uint32_t b_loff = ((uint32_t)(warpn * 64 + (lane & 15)) * LSTR + ((lane >> 4) << 3)) * 2;

    issue(0);
    issue(1);
    for (int it = 0; it < 24; it++) {
        if (it == 23) { CPA_WAIT(0); } else { CPA_WAIT(1); }
        __syncthreads();
        if (it < 22) issue(it + 2);

        const int st = it % 3;
        const uint32_t ab = smb + (uint32_t)(st * 2 * LIN_STAGE_H) * 2 + a_loff;
        const uint32_t bb = smb + (uint32_t)(st * 2 * LIN_STAGE_H + LIN_STAGE_H) * 2 + b_loff;

#pragma unroll
        for (int kc = 0; kc < 2; kc++) {
            uint32_t afr[2][4];
#pragma unroll
            for (int mt = 0; mt < 2; mt++)
                ldsm4(afr[mt][0], afr[mt][1], afr[mt][2], afr[mt][3],
                      ab + ((uint32_t)(mt * 16 * LSTR + kc * 16) << 1));
#pragma unroll
            for (int ntp = 0; ntp < 4; ntp++) {
                uint32_t m0, m1, m2, m3;
                ldsm4(m0, m1, m2, m3, bb + ((uint32_t)(ntp * 16 * LSTR + kc * 16) << 1));
                uint32_t b0[2] = {m0, m2}, b1[2] = {m1, m3};
#pragma unroll
                for (int mt = 0; mt < 2; mt++) {
                    mma16(acc[mt][2 * ntp],     afr[mt], b0);
                    mma16(acc[mt][2 * ntp + 1], afr[mt], b1);
                }
            }
        }
    }

#pragma unroll
    for (int mt = 0; mt < 2; mt++) {
        const int row0 = bm + warpm * 32 + mt * 16 + g;
#pragma unroll
        for (int nt = 0; nt < 8; nt++) {
            const int col = bn + warpn * 64 + nt * 8 + 2 * tig;
            const float bx = bias[col], by = bias[col + 1];
            *(uint32_t*)&Y[(size_t)row0 * Dc + col] =
                h2pack(acc[mt][nt][0] + bx, acc[mt][nt][1] + by);
            *(uint32_t*)&Y[(size_t)(row0 + 8) * Dc + col] =
                h2pack(acc[mt][nt][2] + bx, acc[mt][nt][3] + by);
        }
    }
}

// ----------------------------------------------------------------------------
// Flash attention (fp16 m16n8k16): fixed-shift f32 softmax; l via per-lane
// partial sums (single epilogue quad-reduce). lq converted f32->fp16 in the
// prologue (prep no longer touches it). 32 q-rows/warp, KT=32, occ 1.
// ----------------------------------------------------------------------------
#define KT 32
#define NT 64                           // Sc / KT
#define KSTR 136
#define VSTR 72
#define KSBUF (KT * KSTR)               // 4352 halfs
#define VSBUF (KT * VSTR)               // 2304 halfs
#define KS_H 0                          // 4 bufs
#define VS_H (4 * KSBUF)                // 17408
#define MS_B ((VS_H + 4 * VSBUF) * 2)   // 53248 bytes
#define QS_B (MS_B + 4 * KT * 4)        // 53760 bytes (Q staging region)
#define ATT_SMEM (QS_B + 256 * KSTR * 2)  // 123392 B

__global__ __launch_bounds__(256, 1) void attn_tc(
    const float* __restrict__ lq32,
    float* __restrict__ out)
{
    extern __shared__ __align__(16) __half smh[];
    const uint32_t smb = smem_u32(smh);
    float* msf = (float*)((char*)smh + MS_B);

    const int tid = threadIdx.x;
    const int wid = tid >> 5, lane = tid & 31;
    const int g = lane >> 2, tig = lane & 3;

    const int b = blockIdx.z, h = blockIdx.y, q0 = blockIdx.x * 256;
    const int hoff = h * HDc;

    auto issue_tile = [&](int t) {
        const int s = t & 3;
        const size_t rb = (size_t)(b * Sc + t * KT) * Dc + hoff;
        const __half* gk  = g_k  + rb;
        const __half* glk = g_lk + rb;
        const __half* gv  = g_v  + rb;
        const uint32_t ksb = smb + (uint32_t)(KS_H + s * KSBUF) * 2;
        const uint32_t vsb = smb + (uint32_t)(VS_H + s * VSBUF) * 2;
#pragma unroll
        for (int i = 0; i < 2; i++) {
            int id = tid + i * 256;
            int row = id >> 4, ch = id & 15;
            const __half* src = (ch < 8) ? (gk + (size_t)row * Dc + ch * 8)
                                         : (glk + (size_t)row * Dc + (ch - 8) * 8);
            cpa16(ksb + (uint32_t)(row * KSTR + ch * 8) * 2, src);
        }
        {
            int row = tid >> 3, ch = tid & 7;
            cpa16(vsb + (uint32_t)(row * VSTR + ch * 8) * 2, gv + (size_t)row * Dc + ch * 8);
        }
        if (tid < 8)
            cpa16(smb + (uint32_t)MS_B + (uint32_t)(s * KT + tid * 4) * 4,
                  g_mkl + (size_t)b * Sc + t * KT + tid * 4);
        CPA_COMMIT();
    };

    // ---- Q staging: q half via cp.async (fp16); lq half LDG f32 -> cvt -> STS
    {
        const size_t rb = (size_t)(b * Sc + q0) * Dc + hoff;
#pragma unroll
        for (int i = 0; i < 16; i++) {
            int id = tid + i * 256;
            int row = id >> 4, ch = id & 15;
            if (ch < 8) {
                cpa16(smb + (uint32_t)QS_B + (uint32_t)(row * KSTR + ch * 8) * 2,
                      g_q + rb + (size_t)row * Dc + ch * 8);
            } else {
                const float* src = lq32 + rb + (size_t)row * Dc + (ch - 8) * 8;
                float4 v0 = *(const float4*)src;
                float4 v1 = *(const float4*)(src + 4);
                uint4 o;
                o.x = h2pack(v0.x, v0.y);
                o.y = h2pack(v0.z, v0.w);
                o.z = h2pack(v1.x, v1.y);
                o.w = h2pack(v1.z, v1.w);
                *(uint4*)((char*)smh + (size_t)(QS_B + (row * KSTR + ch * 8) * 2)) = o;
            }
        }
        CPA_COMMIT();
    }
    issue_tile(0);

    // ---- Q fragments -> registers (32 rows/warp: two 16-row frags per kc)
    CPA_WAIT(1);            // Q-staging cpa group complete (tile0 in flight)
    __syncthreads();
    uint32_t qa[8][2][4];
    {
        const uint32_t qlane = smb + (uint32_t)QS_B +
            ((uint32_t)((wid * 32 + (lane & 15)) * KSTR + ((lane >> 4) << 3)) << 1);
#pragma unroll
        for (int kc = 0; kc < 8; kc++) {
            ldsm4(qa[kc][0][0], qa[kc][0][1], qa[kc][0][2], qa[kc][0][3],
                  qlane + ((uint32_t)(kc * 16) << 1));
            ldsm4(qa[kc][1][0], qa[kc][1][1], qa[kc][1][2], qa[kc][1][3],
                  qlane + ((uint32_t)(16 * KSTR + kc * 16) << 1));
        }
    }

    float oacc[2][8][4];
    float l_part[2][2];       // per-lane partial sums: [mt][row-half g / g+8]
    uint32_t pold[2][2][4];   // [kb][mt][4]
#pragma unroll
    for (int mt = 0; mt < 2; mt++) {
#pragma unroll
        for (int nt = 0; nt < 8; nt++)
#pragma unroll
            for (int c = 0; c < 4; c++) oacc[mt][nt][c] = 0.0f;
        l_part[mt][0] = 0.0f; l_part[mt][1] = 0.0f;
#pragma unroll
        for (int kb = 0; kb < 2; kb++)
#pragma unroll
            for (int c = 0; c < 4; c++) pold[kb][mt][c] = 0u;
    }

    const uint32_t k_loff = ((uint32_t)(lane & 15) * KSTR + ((lane >> 4) << 3)) << 1;
    const uint32_t v_loff = ((uint32_t)((lane & 7) + (((lane >> 3) & 1) << 3)) * VSTR
                             + ((lane >> 4) << 3)) << 1;
    const float C1 = 0.18033688011112042f;   // 0.125 * log2(e)

    for (int t = 0; t < NT; t++) {
        if (t < NT - 1) { issue_tile(t + 1); CPA_WAIT(1); }
        else            { CPA_WAIT(0); }
        __syncthreads();

        const int s = t & 3, sp = (t - 1) & 3;
        const uint32_t ksl = smb + ((uint32_t)(KS_H + s * KSBUF) << 1) + k_loff;
        const uint32_t vsl = smb + ((uint32_t)(VS_H + sp * VSBUF) << 1) + v_loff;
        const float* ms = msf + s * KT;

        // ---- QK(t): 32q x 32k x 128d  (64 mma16, 16 ldsm4)
        float sacc[2][4][4];
#pragma unroll
        for (int mt = 0; mt < 2; mt++)
#pragma unroll
            for (int nt = 0; nt < 4; nt++)
#pragma unroll
                for (int c = 0; c < 4; c++) sacc[mt][nt][c] = 0.0f;

#pragma unroll
        for (int kc = 0; kc < 8; kc++) {
#pragma unroll
            for (int nt2 = 0; nt2 < 2; nt2++) {
                uint32_t m0r, m1r, m2r, m3r;
                ldsm4(m0r, m1r, m2r, m3r,
                      ksl + ((uint32_t)(nt2 * 16 * KSTR + kc * 16) << 1));
                uint32_t b0[2] = {m0r, m2r}, b1[2] = {m1r, m3r};
#pragma unroll
                for (int mt = 0; mt < 2; mt++) {
                    mma16(sacc[mt][2 * nt2],     qa[kc][mt], b0);
                    mma16(sacc[mt][2 * nt2 + 1], qa[kc][mt], b1);
                }
            }
        }

        // ---- PV(t-1): O += P @ V
        if (t > 0) {
#pragma unroll
            for (int kb = 0; kb < 2; kb++) {
#pragma unroll
                for (int nt2 = 0; nt2 < 4; nt2++) {
                    uint32_t m0r, m1r, m2r, m3r;
                    ldsm4t(m0r, m1r, m2r, m3r,
                           vsl + ((uint32_t)(kb * 16 * VSTR + nt2 * 16) << 1));
                    uint32_t b0[2] = {m0r, m1r}, b1[2] = {m2r, m3r};
#pragma unroll
                    for (int mt = 0; mt < 2; mt++) {
                        mma16(oacc[mt][2 * nt2],     pold[kb][mt], b0);
                        mma16(oacc[mt][2 * nt2 + 1], pold[kb][mt], b1);
                    }
                }
            }
        }

        // ---- softmax(t): fixed shift, f32 EX2; per-lane partial l sums only
#pragma unroll
        for (int mt = 0; mt < 2; mt++) {
            float s0 = 0.0f, s1 = 0.0f;
#pragma unroll
            for (int nt = 0; nt < 4; nt++) {
                const float mk0 = ms[nt * 8 + 2 * tig], mk1 = ms[nt * 8 + 2 * tig + 1];
                sacc[mt][nt][0] = ex2(sacc[mt][nt][0] * C1 + mk0);
                sacc[mt][nt][1] = ex2(sacc[mt][nt][1] * C1 + mk1);
                sacc[mt][nt][2] = ex2(sacc[mt][nt][2] * C1 + mk0);
                sacc[mt][nt][3] = ex2(sacc[mt][nt][3] * C1 + mk1);
                s0 += sacc[mt][nt][0] + sacc[mt][nt][1];
                s1 += sacc[mt][nt][2] + sacc[mt][nt][3];
            }
            l_part[mt][0] += s0;
            l_part[mt][1] += s1;
        }
#pragma unroll
        for (int kb = 0; kb < 2; kb++)
#pragma unroll
            for (int mt = 0; mt < 2; mt++) {
                pold[kb][mt][0] = h2pack(sacc[mt][2 * kb][0],     sacc[mt][2 * kb][1]);
                pold[kb][mt][1] = h2pack(sacc[mt][2 * kb][2],     sacc[mt][2 * kb][3]);
                pold[kb][mt][2] = h2pack(sacc[mt][2 * kb + 1][0], sacc[mt][2 * kb + 1][1]);
                pold[kb][mt][3] = h2pack(sacc[mt][2 * kb + 1][2], sacc[mt][2 * kb + 1][3]);
            }
    }

    // ---- drain: PV(NT-1)
    {
        const int sp = (NT - 1) & 3;
        const uint32_t vsl = smb + ((uint32_t)(VS_H + sp * VSBUF) << 1) + v_loff;
#pragma unroll
        for (int kb = 0; kb < 2; kb++) {
#pragma unroll
            for (int nt2 = 0; nt2 < 4; nt2++) {
                uint32_t m0r, m1r, m2r, m3r;
                ldsm4t(m0r, m1r, m2r, m3r,
                       vsl + ((uint32_t)(kb * 16 * VSTR + nt2 * 16) << 1));
                uint32_t b0[2] = {m0r, m1r}, b1[2] = {m2r, m3r};
#pragma unroll
                for (int mt = 0; mt < 2; mt++) {
                    mma16(oacc[mt][2 * nt2],     pold[kb][mt], b0);
                    mma16(oacc[mt][2 * nt2 + 1], pold[kb][mt], b1);
                }
            }
        }
    }

    // ---- epilogue: ONE quad reduction for l, then normalize + store
#pragma unroll
    for (int mt = 0; mt < 2; mt++) {
        float l0 = l_part[mt][0], l1 = l_part[mt][1];
        l0 += __shfl_xor_sync(0xffffffffu, l0, 1);
        l0 += __shfl_xor_sync(0xffffffffu, l0, 2);
        l1 += __shfl_xor_sync(0xffffffffu, l1, 1);
        l1 += __shfl_xor_sync(0xffffffffu, l1, 2);
        const float i0 = 1.0f / l0, i1 = 1.0f / l1;
        const int row = b * Sc + q0 + wid * 32 + mt * 16 + g;
        float* ob = out + (size_t)row * Dc + hoff;
#pragma unroll
        for (int nt = 0; nt < 8; nt++) {
            const int col = nt * 8 + 2 * tig;
            *(float2*)&ob[col] = make_float2(oacc[mt][nt][0] * i0, oacc[mt][nt][1] * i0);
            *(float2*)&ob[(size_t)8 * Dc + col] =
                make_float2(oacc[mt][nt][2] * i1, oacc[mt][nt][3] * i1);
        }
    }
}

// ----------------------------------------------------------------------------
// Launch
// ----------------------------------------------------------------------------
extern "C" void kernel_launch(void* const* d_in, const int* in_sizes, int n_in,
                              void* d_out, int out_size)
{
    const float* hs   = (const float*)d_in[0];
    const float* lq   = (const float*)d_in[1];
    const float* lk   = (const float*)d_in[2];
    const float* mask = (const float*)d_in[3];
    const float* Wq   = (const float*)d_in[4];
    const float* bq   = (const float*)d_in[5];
    const float* Wk   = (const float*)d_in[6];
    const float* bk   = (const float*)d_in[7];
    const float* Wv   = (const float*)d_in[8];
    const float* bv   = (const float*)d_in[9];
    float* out = (float*)d_out;

    dim3 gp(512, 6);
    round_all<<<gp, 256>>>(hs, lk, Wq, Wk, Wv, mask);

    cudaFuncSetAttribute(linear_tc, cudaFuncAttributeMaxDynamicSharedMemorySize, LIN_SMEM);
    dim3 gl(Dc / 128, Mrows / 128, 3);   // (6, 64, 3)
    linear_tc<<<gl, 256, LIN_SMEM>>>(bq, bk, bv);

    cudaFuncSetAttribute(attn_tc, cudaFuncAttributeMaxDynamicSharedMemorySize, ATT_SMEM);
    dim3 ga(Sc / 256, Hc, Bc);           // (8, 12, 4) = 384 CTAs
    attn_tc<<<ga, 256, ATT_SMEM>>>(lq, out);
}